// round 5
// baseline (speedup 1.0000x reference)
#include <cuda_runtime.h>
#include <cuda_bf16.h>

// MSE + SSIM loss, pred/target: [32,1,512,512] fp32.
// loss = 0.6*mean((p-t)^2) + 0.4*(1 - mean(ssim_map)), ssim via 11x11 gaussian
// (sigma=1.5) VALID blur -> [32,502,502].
//
// Structure:
//   k_init  : zero global double accumulators (graph-replay safe)
//   k_mse   : float4 grid-stride reduce of (p-t)^2 -> atomicAdd(double)
//   k_ssim  : one CTA per 32x32 output tile; separable blur fully in smem
//   k_final : combine into d_out[0]

#define IMG 512
#define OUT 502            // 512 - 10 (valid conv, 11-tap)
#define TILE 32
#define HALO_DIM 42        // TILE + 10
#define BATCH 32

__device__ double g_mse_sum;
__device__ double g_ssim_sum;

__device__ __forceinline__ void gauss_weights(float g[11]) {
    float s = 0.0f;
#pragma unroll
    for (int i = 0; i < 11; i++) {
        float d = (float)i - 5.0f;
        g[i] = expf(-d * d / (2.0f * 1.5f * 1.5f));
        s += g[i];
    }
    float inv = 1.0f / s;
#pragma unroll
    for (int i = 0; i < 11; i++) g[i] *= inv;
}

__global__ void k_init() {
    g_mse_sum = 0.0;
    g_ssim_sum = 0.0;
}

// ---------------- MSE ----------------
__global__ void k_mse(const float* __restrict__ pred,
                      const float* __restrict__ targ, int n4) {
    int idx = blockIdx.x * blockDim.x + threadIdx.x;
    float local = 0.0f;
    const float4* p4 = reinterpret_cast<const float4*>(pred);
    const float4* t4 = reinterpret_cast<const float4*>(targ);
    for (int i = idx; i < n4; i += gridDim.x * blockDim.x) {
        float4 p = p4[i];
        float4 t = t4[i];
        float d0 = p.x - t.x, d1 = p.y - t.y, d2 = p.z - t.z, d3 = p.w - t.w;
        local += d0 * d0 + d1 * d1 + d2 * d2 + d3 * d3;
    }
    // warp reduce
#pragma unroll
    for (int off = 16; off > 0; off >>= 1)
        local += __shfl_down_sync(0xFFFFFFFFu, local, off);
    __shared__ float warp_sums[8];
    int lane = threadIdx.x & 31, wid = threadIdx.x >> 5;
    if (lane == 0) warp_sums[wid] = local;
    __syncthreads();
    if (wid == 0) {
        float v = (lane < (blockDim.x >> 5)) ? warp_sums[lane] : 0.0f;
#pragma unroll
        for (int off = 4; off > 0; off >>= 1)
            v += __shfl_down_sync(0xFFFFFFFFu, v, off);
        if (lane == 0) atomicAdd(&g_mse_sum, (double)v);
    }
}

// ---------------- SSIM ----------------
__global__ __launch_bounds__(256, 4)
void k_ssim(const float* __restrict__ pred, const float* __restrict__ targ) {
    __shared__ float sp[HALO_DIM][HALO_DIM + 1];   // pred halo tile
    __shared__ float st[HALO_DIM][HALO_DIM + 1];   // target halo tile
    __shared__ float hh[5][HALO_DIM][TILE + 1];    // horizontal-blur channels

    const int t = threadIdx.x;                     // 256 threads
    const int b = blockIdx.z;
    const int ox0 = blockIdx.x * TILE;
    const int oy0 = blockIdx.y * TILE;
    const float* P = pred + (size_t)b * IMG * IMG;
    const float* T = targ + (size_t)b * IMG * IMG;

    float g[11];
    gauss_weights(g);

    // 1) load 42x42 halo tiles (zero-fill out-of-range; those only feed
    //    invalid outputs which are excluded from the reduction)
    for (int idx = t; idx < HALO_DIM * HALO_DIM; idx += 256) {
        int r = idx / HALO_DIM, c = idx % HALO_DIM;
        int gy = oy0 + r, gx = ox0 + c;
        float pv = 0.0f, tv = 0.0f;
        if (gy < IMG && gx < IMG) {
            int o = gy * IMG + gx;
            pv = P[o];
            tv = T[o];
        }
        sp[r][c] = pv;
        st[r][c] = tv;
    }
    __syncthreads();

    // 2) horizontal pass: 42 rows x 32 cols, 4 consecutive cols per task so
    //    14 loads serve 4 outputs x 11 taps per array.
    for (int task = t; task < HALO_DIM * 8; task += 256) {
        int r = task >> 3;
        int c0 = (task & 7) * 4;
        float pv[14], tv[14];
#pragma unroll
        for (int i = 0; i < 14; i++) { pv[i] = sp[r][c0 + i]; tv[i] = st[r][c0 + i]; }
#pragma unroll
        for (int j = 0; j < 4; j++) {
            float ap = 0.f, at = 0.f, app = 0.f, att = 0.f, apt = 0.f;
#pragma unroll
            for (int k = 0; k < 11; k++) {
                float w = g[k], p = pv[j + k], q = tv[j + k];
                ap  = fmaf(w, p, ap);
                at  = fmaf(w, q, at);
                app = fmaf(w * p, p, app);
                att = fmaf(w * q, q, att);
                apt = fmaf(w * p, q, apt);
            }
            hh[0][r][c0 + j] = ap;
            hh[1][r][c0 + j] = at;
            hh[2][r][c0 + j] = app;
            hh[3][r][c0 + j] = att;
            hh[4][r][c0 + j] = apt;
        }
    }
    __syncthreads();

    // 3) vertical pass: thread (tx, ty) computes 4 consecutive output rows
    const int tx = t & 31;
    const int y0 = (t >> 5) * 4;
    float acc[5][4];
#pragma unroll
    for (int a = 0; a < 5; a++) {
        float v[14];
#pragma unroll
        for (int i = 0; i < 14; i++) v[i] = hh[a][y0 + i][tx];
#pragma unroll
        for (int j = 0; j < 4; j++) {
            float s = 0.f;
#pragma unroll
            for (int k = 0; k < 11; k++) s = fmaf(g[k], v[j + k], s);
            acc[a][j] = s;
        }
    }

    // 4) ssim map + partial sum
    const float C1 = 1e-4f;       // (0.01)^2
    const float C2 = 9e-4f;       // (0.03)^2
    float lsum = 0.0f;
    const int ox = ox0 + tx;
#pragma unroll
    for (int j = 0; j < 4; j++) {
        int oy = oy0 + y0 + j;
        if (ox < OUT && oy < OUT) {
            float m1 = acc[0][j], m2 = acc[1][j];
            float m1sq = m1 * m1, m2sq = m2 * m2, m12 = m1 * m2;
            float s1 = acc[2][j] - m1sq;
            float s2 = acc[3][j] - m2sq;
            float s12 = acc[4][j] - m12;
            float num = (2.0f * m12 + C1) * (2.0f * s12 + C2);
            float den = (m1sq + m2sq + C1) * (s1 + s2 + C2) + 1e-6f;
            lsum += __fdividef(num, den);
        }
    }

    // 5) block reduction -> one double atomic
#pragma unroll
    for (int off = 16; off > 0; off >>= 1)
        lsum += __shfl_down_sync(0xFFFFFFFFu, lsum, off);
    __shared__ float warp_sums[8];
    int lane = t & 31, wid = t >> 5;
    if (lane == 0) warp_sums[wid] = lsum;
    __syncthreads();
    if (wid == 0) {
        float v = (lane < 8) ? warp_sums[lane] : 0.0f;
#pragma unroll
        for (int off = 4; off > 0; off >>= 1)
            v += __shfl_down_sync(0xFFFFFFFFu, v, off);
        if (lane == 0) atomicAdd(&g_ssim_sum, (double)v);
    }
}

// ---------------- combine ----------------
__global__ void k_final(float* __restrict__ out) {
    const double n_mse = (double)BATCH * IMG * IMG;
    const double n_ssim = (double)BATCH * OUT * OUT;
    double mse_mean = g_mse_sum / n_mse;
    double ssim_mean = g_ssim_sum / n_ssim;
    out[0] = (float)(0.6 * mse_mean + 0.4 * (1.0 - ssim_mean));
}

extern "C" void kernel_launch(void* const* d_in, const int* in_sizes, int n_in,
                              void* d_out, int out_size) {
    const float* pred = (const float*)d_in[0];
    const float* targ = (const float*)d_in[1];
    float* out = (float*)d_out;

    k_init<<<1, 1>>>();

    int n = in_sizes[0];            // 8388608
    int n4 = n / 4;
    int mse_blocks = 2048;
    k_mse<<<mse_blocks, 256>>>(pred, targ, n4);

    dim3 grid((OUT + TILE - 1) / TILE, (OUT + TILE - 1) / TILE, BATCH); // 16,16,32
    k_ssim<<<grid, 256>>>(pred, targ);

    k_final<<<1, 1>>>(out);
}

// round 6
// speedup vs baseline: 1.2267x; 1.2267x over previous
#include <cuda_runtime.h>
#include <cuda_bf16.h>

// Fused MSE + SSIM loss, pred/target: [32,1,512,512] fp32.
// loss = 0.6*mean((p-t)^2) + 0.4*(1 - mean(ssim_map)); ssim via 11x11
// gaussian (sigma=1.5) VALID separable blur -> [32,502,502].
//
// Single kernel: one CTA per 32x32 output tile (16x16x32 grid).
//  - load 42x42 halo of pred/target to smem
//  - fused MSE over the owned 32x32 region (tiles partition 512^2 exactly)
//  - horizontal 11-tap pass (5 channels: p,t,p2,t2,pt) -> smem, streaming
//    k-outer form with compile-time gaussian weights => FFMA-imm (rt=1)
//  - vertical 11-tap pass in registers, ssim map, block reduce
//  - per-block atomicAdd(double) into 64 slots; last CTA combines + resets

#define IMG 512
#define OUT 502            // 512 - 10
#define TILE 32
#define HALO 42            // TILE + 10
#define NB   (16 * 16 * 32)

// Gaussian(sigma=1.5, 11 taps), normalized; matches float32 reference to ~1e-7.
#define GW0 0.001028380f
#define GW1 0.007598758f
#define GW2 0.036000773f
#define GW3 0.109360703f
#define GW4 0.213005539f
#define GW5 0.266011725f

__device__ double g_slots[128];     // [0:64) mse partials, [64:128) ssim partials
__device__ unsigned int g_count;    // statically zero; reset by last CTA

__global__ __launch_bounds__(256, 4)
void k_main(const float* __restrict__ pred, const float* __restrict__ targ,
            float* __restrict__ out) {
    __shared__ float sp[HALO][HALO + 1];       // stride 43: conflict-free
    __shared__ float st[HALO][HALO + 1];
    __shared__ float hh[5][HALO][TILE + 1];    // stride 33: conflict-free
    __shared__ float red[16];
    __shared__ int s_last;

    const float GW[11] = {GW0, GW1, GW2, GW3, GW4, GW5, GW4, GW3, GW2, GW1, GW0};

    const int t = threadIdx.x;                 // 256 threads
    const int ox0 = blockIdx.x * TILE;
    const int oy0 = blockIdx.y * TILE;
    const float* P = pred + (size_t)blockIdx.z * (IMG * IMG);
    const float* T = targ + (size_t)blockIdx.z * (IMG * IMG);

    // ---- 1) load 42x42 halo (zero-fill OOB; only feeds excluded outputs) ----
    for (int idx = t; idx < HALO * HALO; idx += 256) {
        int r = idx / HALO, c = idx - r * HALO;
        int gy = oy0 + r, gx = ox0 + c;
        float pv = 0.0f, tv = 0.0f;
        if (gy < IMG && gx < IMG) {
            int o = gy * IMG + gx;
            pv = P[o];
            tv = T[o];
        }
        sp[r][c] = pv;
        st[r][c] = tv;
    }
    __syncthreads();

    // ---- 2) fused MSE over owned 32x32 region ----
    float msel = 0.0f;
#pragma unroll
    for (int it = 0; it < 4; it++) {
        int r = (t >> 5) + it * 8, c = t & 31;
        float d = sp[r][c] - st[r][c];
        msel = fmaf(d, d, msel);
    }

    // ---- 3) horizontal pass: 42 rows x 8 col-groups of 4 outputs ----
    // Streaming k-outer: 20 accumulators, one (p,t) pixel in flight.
    for (int task = t; task < HALO * 8; task += 256) {
        int r = task >> 3;
        int c0 = (task & 7) * 4;
        float acc[5][4];
#pragma unroll
        for (int a = 0; a < 5; a++)
#pragma unroll
            for (int j = 0; j < 4; j++) acc[a][j] = 0.0f;
#pragma unroll
        for (int i = 0; i < 14; i++) {
            float p = sp[r][c0 + i];
            float q = st[r][c0 + i];
            float pp = p * p, qq = q * q, pq = p * q;
#pragma unroll
            for (int j = 0; j < 4; j++) {
                int k = i - j;
                if (k >= 0 && k < 11) {
                    acc[0][j] = fmaf(GW[k], p,  acc[0][j]);
                    acc[1][j] = fmaf(GW[k], q,  acc[1][j]);
                    acc[2][j] = fmaf(GW[k], pp, acc[2][j]);
                    acc[3][j] = fmaf(GW[k], qq, acc[3][j]);
                    acc[4][j] = fmaf(GW[k], pq, acc[4][j]);
                }
            }
        }
#pragma unroll
        for (int j = 0; j < 4; j++) {
            hh[0][r][c0 + j] = acc[0][j];
            hh[1][r][c0 + j] = acc[1][j];
            hh[2][r][c0 + j] = acc[2][j];
            hh[3][r][c0 + j] = acc[3][j];
            hh[4][r][c0 + j] = acc[4][j];
        }
    }
    __syncthreads();

    // ---- 4) vertical pass: 4 consecutive output rows per thread ----
    const int tx = t & 31;
    const int y0 = (t >> 5) * 4;
    float vac[5][4];
#pragma unroll
    for (int a = 0; a < 5; a++)
#pragma unroll
        for (int j = 0; j < 4; j++) vac[a][j] = 0.0f;
#pragma unroll
    for (int a = 0; a < 5; a++) {
#pragma unroll
        for (int i = 0; i < 14; i++) {
            float v = hh[a][y0 + i][tx];
#pragma unroll
            for (int j = 0; j < 4; j++) {
                int k = i - j;
                if (k >= 0 && k < 11) vac[a][j] = fmaf(GW[k], v, vac[a][j]);
            }
        }
    }

    // ---- 5) ssim map + partial sum ----
    const float C1 = 1e-4f;   // (0.01)^2
    const float C2 = 9e-4f;   // (0.03)^2
    float lsum = 0.0f;
    const int ox = ox0 + tx;
#pragma unroll
    for (int j = 0; j < 4; j++) {
        int oy = oy0 + y0 + j;
        if (ox < OUT && oy < OUT) {
            float m1 = vac[0][j], m2 = vac[1][j];
            float m1sq = m1 * m1, m2sq = m2 * m2, m12 = m1 * m2;
            float s1 = vac[2][j] - m1sq;
            float s2 = vac[3][j] - m2sq;
            float s12 = vac[4][j] - m12;
            float num = (2.0f * m12 + C1) * (2.0f * s12 + C2);
            float den = (m1sq + m2sq + C1) * (s1 + s2 + C2) + 1e-6f;
            lsum += __fdividef(num, den);
        }
    }

    // ---- 6) block reduce (mse, ssim) -> slot atomics ----
#pragma unroll
    for (int off = 16; off > 0; off >>= 1) {
        msel += __shfl_down_sync(0xFFFFFFFFu, msel, off);
        lsum += __shfl_down_sync(0xFFFFFFFFu, lsum, off);
    }
    int lane = t & 31, wid = t >> 5;
    if (lane == 0) { red[wid] = msel; red[8 + wid] = lsum; }
    __syncthreads();
    if (t == 0) {
        float ms = 0.0f, ls = 0.0f;
#pragma unroll
        for (int w = 0; w < 8; w++) { ms += red[w]; ls += red[8 + w]; }
        int bid = blockIdx.x + 16 * blockIdx.y + 256 * blockIdx.z;
        int slot = bid & 63;
        atomicAdd(&g_slots[slot],      (double)ms);
        atomicAdd(&g_slots[64 + slot], (double)ls);
        __threadfence();
        unsigned int old = atomicAdd(&g_count, 1u);
        s_last = (old == NB - 1) ? 1 : 0;
    }
    __syncthreads();

    // ---- 7) last CTA: combine, write output, reset state for next replay ----
    if (s_last) {
        __threadfence();
        if (t < 32) {
            volatile double* vs = g_slots;
            double m = vs[t] + vs[t + 32];
            double s = vs[64 + t] + vs[96 + t];
#pragma unroll
            for (int off = 16; off > 0; off >>= 1) {
                m += __shfl_down_sync(0xFFFFFFFFu, m, off);
                s += __shfl_down_sync(0xFFFFFFFFu, s, off);
            }
            if (t == 0) {
                double mse_mean  = m / ((double)32 * IMG * IMG);
                double ssim_mean = s / ((double)32 * OUT * OUT);
                out[0] = (float)(0.6 * mse_mean + 0.4 * (1.0 - ssim_mean));
            }
        }
        __syncthreads();
        if (t < 128) ((volatile double*)g_slots)[t] = 0.0;
        if (t == 0) g_count = 0u;
    }
}

extern "C" void kernel_launch(void* const* d_in, const int* in_sizes, int n_in,
                              void* d_out, int out_size) {
    const float* pred = (const float*)d_in[0];
    const float* targ = (const float*)d_in[1];
    dim3 grid(16, 16, 32);   // (OUT/TILE ceil, OUT/TILE ceil, batch)
    k_main<<<grid, 256>>>(pred, targ, (float*)d_out);
}

// round 9
// speedup vs baseline: 1.4013x; 1.1424x over previous
#include <cuda_runtime.h>
#include <cuda_bf16.h>

// Fused MSE + SSIM loss, pred/target: [32,1,512,512] fp32.
// loss = 0.6*mean((p-t)^2) + 0.4*(1 - mean(ssim_map)); ssim via 11x11
// gaussian (sigma=1.5) VALID separable blur -> [32,502,502].
//
// Single kernel, one CTA per 32x32 output tile (16x16x32 grid).
// s/d reparameterization: s=p+t, d=p-t. Only 4 blur channels needed:
//   bs=blur(s), bd=blur(d), bss=blur(s^2), bdd=blur(d^2)
//   4*mu1mu2        = bs^2 - bd^2
//   2*(mu1^2+mu2^2) = bs^2 + bd^2
//   4*blur(pt)      = bss - bdd
//   2*(blurp2+blurt2) = bss + bdd
// Channels interleaved as float2 in smem -> LDS.64 everywhere.

#define IMG 512
#define OUT 502            // 512 - 10
#define TILE 32
#define HALO 42            // TILE + 10
#define NB   (16 * 16 * 32)

// Gaussian(sigma=1.5, 11 taps), normalized (matches fp32 reference ~1e-7)
#define GW0 0.001028380f
#define GW1 0.007598758f
#define GW2 0.036000773f
#define GW3 0.109360703f
#define GW4 0.213005539f
#define GW5 0.266011725f

__device__ double g_slots[128];     // [0:64) mse partials, [64:128) ssim partials
__device__ unsigned int g_count;    // statically zero; reset by last CTA

__global__ __launch_bounds__(256, 5)
void k_main(const float* __restrict__ pred, const float* __restrict__ targ,
            float* __restrict__ out) {
    __shared__ float2 ssd[HALO][HALO + 1];     // (s, d); stride 43 -> conflict-free
    __shared__ float2 hh1[HALO][TILE + 1];     // (bs, bd)
    __shared__ float2 hh2[HALO][TILE + 1];     // (bss, bdd)
    __shared__ float red[16];
    __shared__ int s_last;

    const float GW[11] = {GW0, GW1, GW2, GW3, GW4, GW5, GW4, GW3, GW2, GW1, GW0};

    const int t = threadIdx.x;                 // 256 threads
    const int ox0 = blockIdx.x * TILE;
    const int oy0 = blockIdx.y * TILE;
    const float* P = pred + (size_t)blockIdx.z * (IMG * IMG);
    const float* T = targ + (size_t)blockIdx.z * (IMG * IMG);

    // ---- 1) halo load, float4-vectorized: 42 rows x 11 float4 groups ----
    // ox0 is a multiple of 32 and IMG of 4 => each float4 is fully in- or
    // fully out-of-range. OOB -> 0 (feeds only excluded outputs).
    for (int idx = t; idx < HALO * 11; idx += 256) {
        int r = idx / 11;
        int c4 = idx - r * 11;
        int gy = oy0 + r, gx = ox0 + c4 * 4;
        float4 p = make_float4(0.f, 0.f, 0.f, 0.f);
        float4 q = make_float4(0.f, 0.f, 0.f, 0.f);
        if (gy < IMG && gx <= IMG - 4) {
            int o = gy * IMG + gx;
            p = *reinterpret_cast<const float4*>(P + o);
            q = *reinterpret_cast<const float4*>(T + o);
        }
        int c = c4 * 4;
        ssd[r][c + 0] = make_float2(p.x + q.x, p.x - q.x);
        ssd[r][c + 1] = make_float2(p.y + q.y, p.y - q.y);
        ssd[r][c + 2] = make_float2(p.z + q.z, p.z - q.z);
        ssd[r][c + 3] = make_float2(p.w + q.w, p.w - q.w);
    }
    __syncthreads();

    // ---- 2) fused MSE over owned 32x32 region (tiles partition 512^2) ----
    float msel = 0.0f;
#pragma unroll
    for (int it = 0; it < 4; it++) {
        float d = ssd[(t >> 5) + it * 8][t & 31].y;
        msel = fmaf(d, d, msel);
    }

    // ---- 3) horizontal pass: 336 tasks (42 rows x 8 col-groups of 4) ----
    // Task iteration 0 handles tasks [0,256); iteration 1 the remaining 80.
    // Interleave the leftover tasks across all 8 warps (t*? mapping) so the
    // straggler work doesn't pile onto warps 0-2.
#pragma unroll
    for (int it = 0; it < 2; it++) {
        int task;
        if (it == 0) {
            task = t;
        } else {
            // 80 leftover tasks 256..335: spread 10 per warp
            int lane = t & 31, wid = t >> 5;
            if (lane >= 10) break;
            task = 256 + wid * 10 + lane;
        }
        int r = task >> 3;
        int c0 = (task & 7) * 4;
        float as[4], ad[4], ass[4], add[4];
#pragma unroll
        for (int j = 0; j < 4; j++) { as[j] = ad[j] = ass[j] = add[j] = 0.0f; }
#pragma unroll
        for (int i = 0; i < 14; i++) {
            float2 v = ssd[r][c0 + i];
            float ss = v.x * v.x, dd = v.y * v.y;
#pragma unroll
            for (int j = 0; j < 4; j++) {
                int k = i - j;
                if (k >= 0 && k < 11) {
                    as[j]  = fmaf(GW[k], v.x, as[j]);
                    ad[j]  = fmaf(GW[k], v.y, ad[j]);
                    ass[j] = fmaf(GW[k], ss,  ass[j]);
                    add[j] = fmaf(GW[k], dd,  add[j]);
                }
            }
        }
#pragma unroll
        for (int j = 0; j < 4; j++) {
            hh1[r][c0 + j] = make_float2(as[j], ad[j]);
            hh2[r][c0 + j] = make_float2(ass[j], add[j]);
        }
    }
    __syncthreads();

    // ---- 4) vertical pass: 4 consecutive output rows per thread ----
    const int tx = t & 31;
    const int y0 = (t >> 5) * 4;
    float bs[4], bd[4], bss[4], bdd[4];
#pragma unroll
    for (int j = 0; j < 4; j++) { bs[j] = bd[j] = bss[j] = bdd[j] = 0.0f; }
#pragma unroll
    for (int i = 0; i < 14; i++) {
        float2 v1 = hh1[y0 + i][tx];
        float2 v2 = hh2[y0 + i][tx];
#pragma unroll
        for (int j = 0; j < 4; j++) {
            int k = i - j;
            if (k >= 0 && k < 11) {
                bs[j]  = fmaf(GW[k], v1.x, bs[j]);
                bd[j]  = fmaf(GW[k], v1.y, bd[j]);
                bss[j] = fmaf(GW[k], v2.x, bss[j]);
                bdd[j] = fmaf(GW[k], v2.y, bdd[j]);
            }
        }
    }

    // ---- 5) ssim map + partial sum ----
    const float C1 = 1e-4f;   // (0.01)^2
    const float C2 = 9e-4f;   // (0.03)^2
    float lsum = 0.0f;
    const int ox = ox0 + tx;
#pragma unroll
    for (int j = 0; j < 4; j++) {
        int oy = oy0 + y0 + j;
        if (ox < OUT && oy < OUT) {
            float A = bs[j] * bs[j];
            float B = bd[j] * bd[j];
            float num1 = 0.5f * (A - B) + C1;                       // 2*mu1mu2 + C1
            float den1 = 0.5f * (A + B) + C1;                       // mu1^2+mu2^2 + C1
            float num2 = 0.5f * ((bss[j] - bdd[j]) - (A - B)) + C2; // 2*sigma12 + C2
            float den2 = 0.5f * ((bss[j] + bdd[j]) - (A + B)) + C2; // s1+s2 + C2
            lsum += __fdividef(num1 * num2, den1 * den2 + 1e-6f);
        }
    }

    // ---- 6) block reduce (mse, ssim) -> slot atomics ----
#pragma unroll
    for (int off = 16; off > 0; off >>= 1) {
        msel += __shfl_down_sync(0xFFFFFFFFu, msel, off);
        lsum += __shfl_down_sync(0xFFFFFFFFu, lsum, off);
    }
    int lane = t & 31, wid = t >> 5;
    if (lane == 0) { red[wid] = msel; red[8 + wid] = lsum; }
    __syncthreads();
    if (t == 0) {
        float ms = 0.0f, ls = 0.0f;
#pragma unroll
        for (int w = 0; w < 8; w++) { ms += red[w]; ls += red[8 + w]; }
        int bid = blockIdx.x + 16 * blockIdx.y + 256 * blockIdx.z;
        int slot = bid & 63;
        atomicAdd(&g_slots[slot],      (double)ms);
        atomicAdd(&g_slots[64 + slot], (double)ls);
        __threadfence();
        unsigned int old = atomicAdd(&g_count, 1u);
        s_last = (old == NB - 1) ? 1 : 0;
    }
    __syncthreads();

    // ---- 7) last CTA: combine, write output, reset state for next replay ----
    if (s_last) {
        __threadfence();
        if (t < 32) {
            volatile double* vs = g_slots;
            double m = vs[t] + vs[t + 32];
            double s = vs[64 + t] + vs[96 + t];
#pragma unroll
            for (int off = 16; off > 0; off >>= 1) {
                m += __shfl_down_sync(0xFFFFFFFFu, m, off);
                s += __shfl_down_sync(0xFFFFFFFFu, s, off);
            }
            if (t == 0) {
                // MSE sums (p-t)^2 = d^2 directly
                double mse_mean  = m / ((double)32 * IMG * IMG);
                double ssim_mean = s / ((double)32 * OUT * OUT);
                out[0] = (float)(0.6 * mse_mean + 0.4 * (1.0 - ssim_mean));
            }
        }
        __syncthreads();
        if (t < 128) ((volatile double*)g_slots)[t] = 0.0;
        if (t == 0) g_count = 0u;
    }
}

extern "C" void kernel_launch(void* const* d_in, const int* in_sizes, int n_in,
                              void* d_out, int out_size) {
    const float* pred = (const float*)d_in[0];
    const float* targ = (const float*)d_in[1];
    dim3 grid(16, 16, 32);
    k_main<<<grid, 256>>>(pred, targ, (float*)d_out);
}

// round 11
// speedup vs baseline: 1.5251x; 1.0883x over previous
#include <cuda_runtime.h>
#include <cuda_bf16.h>

// Fused MSE + SSIM loss, pred/target: [32,1,512,512] fp32.
// loss = 0.6*mean((p-t)^2) + 0.4*(1 - mean(ssim_map)); ssim via 11x11
// gaussian (sigma=1.5) VALID separable blur -> [32,502,502].
//
// One CTA per 32x64 output tile (grid 16x8x32 = 4096 CTAs), 256 threads.
// Centered s/d reparameterization: s' = p+t-1 (centered!), d = p-t.
// 4 blur channels: bs'=blur(s'), bd=blur(d), bss'=blur(s'^2), bdd=blur(d^2).
//   bsf = bs'+1 (= mu1+mu2);  A = bsf^2, B = bd^2
//   2*mu1mu2 + C1        = 0.5*(A-B) + C1
//   mu1^2+mu2^2 + C1     = 0.5*(A+B) + C1
//   U = bss' - bs'^2  (var-of-s, shift-invariant),  V = bdd - bd^2
//   2*sigma12 + C2       = 0.5*(U-V) + C2
//   sigma1+sigma2 + C2   = 0.5*(U+V) + C2
// hh stores all 4 channels as float4 -> LDS.128/STS.128, conflict-free.

#define IMG 512
#define OUT 502            // 512 - 10
#define TW  32             // tile width (outputs)
#define TH  64             // tile height (outputs)
#define HW  42             // TW + 10
#define HH_ 74             // TH + 10
#define SSD_PITCH 43       // float2 elements per ssd row
#define HHP 33             // float4 elements per hh row
#define NB  (16 * 8 * 32)  // 4096 CTAs

#define SMEM_BYTES (HH_ * SSD_PITCH * 8 + HH_ * HHP * 16)   // 25456+39072 = 64528

// Gaussian(sigma=1.5, 11 taps), normalized (matches fp32 reference ~1e-7)
#define GW0 0.001028380f
#define GW1 0.007598758f
#define GW2 0.036000773f
#define GW3 0.109360703f
#define GW4 0.213005539f
#define GW5 0.266011725f

__device__ double g_slots[128];     // [0:64) mse partials, [64:128) ssim partials
__device__ unsigned int g_count;    // statically zero; reset by last CTA

__global__ __launch_bounds__(256, 3)
void k_main(const float* __restrict__ pred, const float* __restrict__ targ,
            float* __restrict__ out) {
    extern __shared__ char smem_raw[];
    float2* ssd = reinterpret_cast<float2*>(smem_raw);                    // [HH_][43]
    float4* hh  = reinterpret_cast<float4*>(smem_raw + HH_ * SSD_PITCH * 8); // [HH_][33]
    __shared__ float red[16];
    __shared__ int s_last;

    const float GW[11] = {GW0, GW1, GW2, GW3, GW4, GW5, GW4, GW3, GW2, GW1, GW0};

    const int t = threadIdx.x;                 // 256 threads
    const int ox0 = blockIdx.x * TW;
    const int oy0 = blockIdx.y * TH;
    const float* P = pred + (size_t)blockIdx.z * (IMG * IMG);
    const float* T = targ + (size_t)blockIdx.z * (IMG * IMG);

    // ---- 1) halo load: 74 rows x 11 float4 groups, centered s' = p+t-1 ----
    // ox0 multiple of 32, IMG multiple of 4 => each float4 fully in/out of
    // range. OOB -> 0 (feeds only excluded outputs).
    for (int idx = t; idx < HH_ * 11; idx += 256) {
        int r = idx / 11;
        int c4 = idx - r * 11;
        int gy = oy0 + r, gx = ox0 + c4 * 4;
        float4 p = make_float4(0.f, 0.f, 0.f, 0.f);
        float4 q = make_float4(0.f, 0.f, 0.f, 0.f);
        bool inb = (gy < IMG) && (gx <= IMG - 4);
        if (inb) {
            int o = gy * IMG + gx;
            p = *reinterpret_cast<const float4*>(P + o);
            q = *reinterpret_cast<const float4*>(T + o);
        }
        float cen = inb ? 1.0f : 0.0f;   // keep s'=0 in OOB region
        int c = c4 * 4;
        float2* row = ssd + r * SSD_PITCH;
        row[c + 0] = make_float2(p.x + q.x - cen, p.x - q.x);
        row[c + 1] = make_float2(p.y + q.y - cen, p.y - q.y);
        row[c + 2] = make_float2(p.z + q.z - cen, p.z - q.z);
        row[c + 3] = make_float2(p.w + q.w - cen, p.w - q.w);
    }
    __syncthreads();

    // ---- 2) fused MSE over owned 32x64 region (tiles partition 512^2) ----
    const int tx = t & 31;
    const int y0 = (t >> 5) * 8;
    float msel = 0.0f;
#pragma unroll
    for (int j = 0; j < 8; j++) {
        float d = ssd[(y0 + j) * SSD_PITCH + tx].y;
        msel = fmaf(d, d, msel);
    }

    // ---- 3) horizontal pass: 592 tasks (74 rows x 8 groups of 4 outputs) ----
    // Warp covers 4 rows x 8 col-groups -> conflict-free STS.128 into hh.
    const int lane = t & 31;
    for (int tb = 0; tb < HH_ * 8; tb += 256) {
        int tau = tb + t;
        if (tau >= HH_ * 8) break;
        int wb = tau >> 5;
        int r = wb * 4 + (lane & 3);
        int c0 = (lane >> 2) * 4;
        if (r < HH_) {
            float as[4], ad[4], ass[4], add[4];
#pragma unroll
            for (int j = 0; j < 4; j++) { as[j] = ad[j] = ass[j] = add[j] = 0.0f; }
            const float2* row = ssd + r * SSD_PITCH;
#pragma unroll
            for (int i = 0; i < 14; i++) {
                float2 v = row[c0 + i];
                float ss = v.x * v.x, dd = v.y * v.y;
#pragma unroll
                for (int j = 0; j < 4; j++) {
                    int k = i - j;
                    if (k >= 0 && k < 11) {
                        as[j]  = fmaf(GW[k], v.x, as[j]);
                        ad[j]  = fmaf(GW[k], v.y, ad[j]);
                        ass[j] = fmaf(GW[k], ss,  ass[j]);
                        add[j] = fmaf(GW[k], dd,  add[j]);
                    }
                }
            }
            float4* hrow = hh + r * HHP;
#pragma unroll
            for (int j = 0; j < 4; j++)
                hrow[c0 + j] = make_float4(as[j], ad[j], ass[j], add[j]);
        }
    }
    __syncthreads();

    // ---- 4) vertical pass: 8 consecutive output rows per thread ----
    float bs[8], bd[8], bss[8], bdd[8];
#pragma unroll
    for (int j = 0; j < 8; j++) { bs[j] = bd[j] = bss[j] = bdd[j] = 0.0f; }
#pragma unroll
    for (int i = 0; i < 18; i++) {
        float4 v = hh[(y0 + i) * HHP + tx];
#pragma unroll
        for (int j = 0; j < 8; j++) {
            int k = i - j;
            if (k >= 0 && k < 11) {
                bs[j]  = fmaf(GW[k], v.x, bs[j]);
                bd[j]  = fmaf(GW[k], v.y, bd[j]);
                bss[j] = fmaf(GW[k], v.z, bss[j]);
                bdd[j] = fmaf(GW[k], v.w, bdd[j]);
            }
        }
    }

    // ---- 5) ssim map + partial sum ----
    const float C1 = 1e-4f;   // (0.01)^2
    const float C2 = 9e-4f;   // (0.03)^2
    float lsum = 0.0f;
    const int ox = ox0 + tx;
#pragma unroll
    for (int j = 0; j < 8; j++) {
        int oy = oy0 + y0 + j;
        if (ox < OUT && oy < OUT) {
            float bsf = bs[j] + 1.0f;              // mu1+mu2
            float A = bsf * bsf;
            float B = bd[j] * bd[j];
            float U = bss[j] - bs[j] * bs[j];      // shift-invariant var sum (s)
            float V = bdd[j] - B;                  // var sum (d)
            float num1 = 0.5f * (A - B) + C1;      // 2*mu1mu2 + C1
            float den1 = 0.5f * (A + B) + C1;      // mu1^2+mu2^2 + C1
            float num2 = 0.5f * (U - V) + C2;      // 2*sigma12 + C2
            float den2 = 0.5f * (U + V) + C2;      // sigma1+sigma2 + C2
            lsum += __fdividef(num1 * num2, den1 * den2 + 1e-6f);
        }
    }

    // ---- 6) block reduce (mse, ssim) -> slot atomics ----
#pragma unroll
    for (int off = 16; off > 0; off >>= 1) {
        msel += __shfl_down_sync(0xFFFFFFFFu, msel, off);
        lsum += __shfl_down_sync(0xFFFFFFFFu, lsum, off);
    }
    int wid = t >> 5;
    if (lane == 0) { red[wid] = msel; red[8 + wid] = lsum; }
    __syncthreads();
    if (t == 0) {
        float ms = 0.0f, ls = 0.0f;
#pragma unroll
        for (int w = 0; w < 8; w++) { ms += red[w]; ls += red[8 + w]; }
        int bid = blockIdx.x + 16 * blockIdx.y + 128 * blockIdx.z;
        int slot = bid & 63;
        atomicAdd(&g_slots[slot],      (double)ms);
        atomicAdd(&g_slots[64 + slot], (double)ls);
        __threadfence();
        unsigned int old = atomicAdd(&g_count, 1u);
        s_last = (old == NB - 1) ? 1 : 0;
    }
    __syncthreads();

    // ---- 7) last CTA: combine, write output, reset state for next replay ----
    if (s_last) {
        __threadfence();
        if (t < 32) {
            volatile double* vs = g_slots;
            double m = vs[t] + vs[t + 32];
            double s = vs[64 + t] + vs[96 + t];
#pragma unroll
            for (int off = 16; off > 0; off >>= 1) {
                m += __shfl_down_sync(0xFFFFFFFFu, m, off);
                s += __shfl_down_sync(0xFFFFFFFFu, s, off);
            }
            if (t == 0) {
                double mse_mean  = m / ((double)32 * IMG * IMG);
                double ssim_mean = s / ((double)32 * OUT * OUT);
                out[0] = (float)(0.6 * mse_mean + 0.4 * (1.0 - ssim_mean));
            }
        }
        __syncthreads();
        if (t < 128) ((volatile double*)g_slots)[t] = 0.0;
        if (t == 0) g_count = 0u;
    }
}

extern "C" void kernel_launch(void* const* d_in, const int* in_sizes, int n_in,
                              void* d_out, int out_size) {
    const float* pred = (const float*)d_in[0];
    const float* targ = (const float*)d_in[1];
    cudaFuncSetAttribute(k_main, cudaFuncAttributeMaxDynamicSharedMemorySize,
                         SMEM_BYTES);
    dim3 grid(16, 8, 32);   // x-tiles, y-bands of 64, batch
    k_main<<<grid, 256, SMEM_BYTES>>>(pred, targ, (float*)d_out);
}

// round 12
// speedup vs baseline: 1.6255x; 1.0658x over previous
#include <cuda_runtime.h>
#include <cuda_bf16.h>

// Fused MSE + SSIM loss, pred/target: [32,1,512,512] fp32.
// loss = 0.6*mean((p-t)^2) + 0.4*(1 - mean(ssim_map)); ssim via 11x11
// gaussian (sigma=1.5) VALID separable blur -> [32,502,502].
//
// One CTA per 32x48 output tile (grid 16x11x32 = 5632 CTAs), 256 threads,
// 4 CTAs/SM (smem 50.6KB, regs <=64).
// Centered s/d reparameterization: s' = p+t-1, d = p-t.
// 4 blur channels: bs'=blur(s'), bd=blur(d), bss'=blur(s'^2), bdd=blur(d^2).
//   bsf = bs'+1 (= mu1+mu2);  A = bsf^2, B = bd^2
//   2*mu1mu2 + C1      = 0.5*(A-B) + C1
//   mu1^2+mu2^2 + C1   = 0.5*(A+B) + C1
//   U = bss' - bs'^2,  V = bdd - bd^2
//   2*sigma12 + C2     = 0.5*(U-V) + C2
//   sigma1+sigma2 + C2 = 0.5*(U+V) + C2
// hh holds all 4 channels as float4 -> LDS.128/STS.128, conflict-free.

#define IMG 512
#define OUT 502            // 512 - 10
#define TW  32             // tile width (outputs)
#define TH  48             // tile height (outputs)
#define HH_ 58             // TH + 10 (halo rows)
#define SSD_PITCH 43       // float2 elements per ssd row
#define HHP 33             // float4 elements per hh row
#define NB  (16 * 11 * 32) // 5632 CTAs

#define SMEM_BYTES (HH_ * SSD_PITCH * 8 + HH_ * HHP * 16)  // 19952+30624 = 50576

// Gaussian(sigma=1.5, 11 taps), normalized (matches fp32 reference ~1e-7)
#define GW0 0.001028380f
#define GW1 0.007598758f
#define GW2 0.036000773f
#define GW3 0.109360703f
#define GW4 0.213005539f
#define GW5 0.266011725f

__device__ double g_slots[128];     // [0:64) mse partials, [64:128) ssim partials
__device__ unsigned int g_count;    // statically zero; reset by last CTA

__global__ __launch_bounds__(256, 4)
void k_main(const float* __restrict__ pred, const float* __restrict__ targ,
            float* __restrict__ out) {
    extern __shared__ char smem_raw[];
    float2* ssd = reinterpret_cast<float2*>(smem_raw);                       // [HH_][43]
    float4* hh  = reinterpret_cast<float4*>(smem_raw + HH_ * SSD_PITCH * 8); // [HH_][33]
    __shared__ float red[16];
    __shared__ int s_last;

    const float GW[11] = {GW0, GW1, GW2, GW3, GW4, GW5, GW4, GW3, GW2, GW1, GW0};

    const int t = threadIdx.x;                 // 256 threads
    const int lane = t & 31;
    const int ox0 = blockIdx.x * TW;
    const int oy0 = blockIdx.y * TH;
    const float* P = pred + (size_t)blockIdx.z * (IMG * IMG);
    const float* T = targ + (size_t)blockIdx.z * (IMG * IMG);

    // ---- 1) halo load: 58 rows x 11 float4 groups, centered s' = p+t-1 ----
    // ox0 multiple of 32, IMG multiple of 4 => each float4 fully in/out of
    // range. OOB -> s'=0, d=0 (feeds only excluded SSIM outputs; d=0 adds
    // nothing to MSE).
    for (int idx = t; idx < HH_ * 11; idx += 256) {
        int r = idx / 11;
        int c4 = idx - r * 11;
        int gy = oy0 + r, gx = ox0 + c4 * 4;
        float4 p = make_float4(0.f, 0.f, 0.f, 0.f);
        float4 q = make_float4(0.f, 0.f, 0.f, 0.f);
        bool inb = (gy < IMG) && (gx <= IMG - 4);
        if (inb) {
            int o = gy * IMG + gx;
            p = *reinterpret_cast<const float4*>(P + o);
            q = *reinterpret_cast<const float4*>(T + o);
        }
        float cen = inb ? 1.0f : 0.0f;
        int c = c4 * 4;
        float2* row = ssd + r * SSD_PITCH;
        row[c + 0] = make_float2(p.x + q.x - cen, p.x - q.x);
        row[c + 1] = make_float2(p.y + q.y - cen, p.y - q.y);
        row[c + 2] = make_float2(p.z + q.z - cen, p.z - q.z);
        row[c + 3] = make_float2(p.w + q.w - cen, p.w - q.w);
    }
    __syncthreads();

    // ---- 2) fused MSE over owned 32x48 region (bands disjoint; rows >=512
    //         are OOB-zero so they contribute 0) ----
    const int tx = t & 31;
    const int y0 = (t >> 5) * 6;               // 8 warps x 6 rows = 48
    float msel = 0.0f;
#pragma unroll
    for (int j = 0; j < 6; j++) {
        float d = ssd[(y0 + j) * SSD_PITCH + tx].y;
        msel = fmaf(d, d, msel);
    }

    // ---- 3) horizontal pass: 464 tasks (58 rows x 8 groups of 4 outputs) ----
    // Warp covers 4 rows x 8 col-groups -> conflict-free STS.128 into hh.
    for (int tb = 0; tb < HH_ * 8; tb += 256) {
        int tau = tb + t;
        if (tau >= HH_ * 8) break;
        int wb = tau >> 5;
        int r = wb * 4 + (lane & 3);
        int c0 = (lane >> 2) * 4;
        if (r < HH_) {
            float as[4], ad[4], ass[4], add[4];
#pragma unroll
            for (int j = 0; j < 4; j++) { as[j] = ad[j] = ass[j] = add[j] = 0.0f; }
            const float2* row = ssd + r * SSD_PITCH;
#pragma unroll
            for (int i = 0; i < 14; i++) {
                float2 v = row[c0 + i];
                float ss = v.x * v.x, dd = v.y * v.y;
#pragma unroll
                for (int j = 0; j < 4; j++) {
                    int k = i - j;
                    if (k >= 0 && k < 11) {
                        as[j]  = fmaf(GW[k], v.x, as[j]);
                        ad[j]  = fmaf(GW[k], v.y, ad[j]);
                        ass[j] = fmaf(GW[k], ss,  ass[j]);
                        add[j] = fmaf(GW[k], dd,  add[j]);
                    }
                }
            }
            float4* hrow = hh + r * HHP;
#pragma unroll
            for (int j = 0; j < 4; j++)
                hrow[c0 + j] = make_float4(as[j], ad[j], ass[j], add[j]);
        }
    }
    __syncthreads();

    // ---- 4) vertical pass: 6 consecutive output rows per thread ----
    float bs[6], bd[6], bss[6], bdd[6];
#pragma unroll
    for (int j = 0; j < 6; j++) { bs[j] = bd[j] = bss[j] = bdd[j] = 0.0f; }
#pragma unroll
    for (int i = 0; i < 16; i++) {
        float4 v = hh[(y0 + i) * HHP + tx];
#pragma unroll
        for (int j = 0; j < 6; j++) {
            int k = i - j;
            if (k >= 0 && k < 11) {
                bs[j]  = fmaf(GW[k], v.x, bs[j]);
                bd[j]  = fmaf(GW[k], v.y, bd[j]);
                bss[j] = fmaf(GW[k], v.z, bss[j]);
                bdd[j] = fmaf(GW[k], v.w, bdd[j]);
            }
        }
    }

    // ---- 5) ssim map + partial sum ----
    const float C1 = 1e-4f;   // (0.01)^2
    const float C2 = 9e-4f;   // (0.03)^2
    float lsum = 0.0f;
    const int ox = ox0 + tx;
#pragma unroll
    for (int j = 0; j < 6; j++) {
        int oy = oy0 + y0 + j;
        if (ox < OUT && oy < OUT) {
            float bsf = bs[j] + 1.0f;              // mu1+mu2
            float A = bsf * bsf;
            float B = bd[j] * bd[j];
            float U = bss[j] - bs[j] * bs[j];      // sigma1^2+sigma2^2+2sigma12
            float V = bdd[j] - B;                  // sigma1^2+sigma2^2-2sigma12
            float num1 = 0.5f * (A - B) + C1;      // 2*mu1mu2 + C1
            float den1 = 0.5f * (A + B) + C1;      // mu1^2+mu2^2 + C1
            float num2 = 0.5f * (U - V) + C2;      // 2*sigma12 + C2
            float den2 = 0.5f * (U + V) + C2;      // sigma1+sigma2 + C2
            lsum += __fdividef(num1 * num2, den1 * den2 + 1e-6f);
        }
    }

    // ---- 6) block reduce (mse, ssim) -> slot atomics ----
#pragma unroll
    for (int off = 16; off > 0; off >>= 1) {
        msel += __shfl_down_sync(0xFFFFFFFFu, msel, off);
        lsum += __shfl_down_sync(0xFFFFFFFFu, lsum, off);
    }
    int wid = t >> 5;
    if (lane == 0) { red[wid] = msel; red[8 + wid] = lsum; }
    __syncthreads();
    if (t == 0) {
        float ms = 0.0f, ls = 0.0f;
#pragma unroll
        for (int w = 0; w < 8; w++) { ms += red[w]; ls += red[8 + w]; }
        int bid = blockIdx.x + 16 * blockIdx.y + 176 * blockIdx.z;
        int slot = bid & 63;
        atomicAdd(&g_slots[slot],      (double)ms);
        atomicAdd(&g_slots[64 + slot], (double)ls);
        __threadfence();
        unsigned int old = atomicAdd(&g_count, 1u);
        s_last = (old == NB - 1) ? 1 : 0;
    }
    __syncthreads();

    // ---- 7) last CTA: combine, write output, reset state for next replay ----
    if (s_last) {
        __threadfence();
        if (t < 32) {
            volatile double* vs = g_slots;
            double m = vs[t] + vs[t + 32];
            double s = vs[64 + t] + vs[96 + t];
#pragma unroll
            for (int off = 16; off > 0; off >>= 1) {
                m += __shfl_down_sync(0xFFFFFFFFu, m, off);
                s += __shfl_down_sync(0xFFFFFFFFu, s, off);
            }
            if (t == 0) {
                double mse_mean  = m / ((double)32 * IMG * IMG);
                double ssim_mean = s / ((double)32 * OUT * OUT);
                out[0] = (float)(0.6 * mse_mean + 0.4 * (1.0 - ssim_mean));
            }
        }
        __syncthreads();
        if (t < 128) ((volatile double*)g_slots)[t] = 0.0;
        if (t == 0) g_count = 0u;
    }
}

extern "C" void kernel_launch(void* const* d_in, const int* in_sizes, int n_in,
                              void* d_out, int out_size) {
    const float* pred = (const float*)d_in[0];
    const float* targ = (const float*)d_in[1];
    cudaFuncSetAttribute(k_main, cudaFuncAttributeMaxDynamicSharedMemorySize,
                         SMEM_BYTES);
    dim3 grid(16, 11, 32);   // x-tiles, y-bands of 48, batch
    k_main<<<grid, 256, SMEM_BYTES>>>(pred, targ, (float*)d_out);
}

// round 13
// speedup vs baseline: 1.6817x; 1.0346x over previous
#include <cuda_runtime.h>
#include <cuda_bf16.h>

// Fused MSE + SSIM loss, pred/target: [32,1,512,512] fp32.
// loss = 0.6*mean((p-t)^2) + 0.4*(1 - mean(ssim_map)); ssim via 11x11
// gaussian (sigma=1.5) VALID separable blur -> [32,502,502].
//
// One CTA per 32x40 output tile (grid 16x13x32 = 6656 CTAs), 256 threads,
// 5 CTAs/SM (smem 43.6KB, regs forced <=51).
// Centered s/d reparameterization: s' = p+t-1, d = p-t.
// 4 blur channels: bs'=blur(s'), bd=blur(d), bss'=blur(s'^2), bdd=blur(d^2).
//   bsf = bs'+1 (= mu1+mu2);  A = bsf^2, B = bd^2
//   2*mu1mu2 + C1      = 0.5*(A-B) + C1
//   mu1^2+mu2^2 + C1   = 0.5*(A+B) + C1
//   U = bss' - bs'^2,  V = bdd - bd^2
//   2*sigma12 + C2     = 0.5*(U-V) + C2
//   sigma1+sigma2 + C2 = 0.5*(U+V) + C2
// hh holds all 4 channels as float4 -> LDS.128/STS.128, conflict-free.

#define IMG 512
#define OUT 502            // 512 - 10
#define TW  32             // tile width (outputs)
#define TH  40             // tile height (outputs)
#define HH_ 50             // TH + 10 (halo rows)
#define SSD_PITCH 43       // float2 elements per ssd row
#define HHP 33             // float4 elements per hh row
#define NQUAD 13           // ceil(HH_/4) row-quads for horizontal pass
#define NB  (16 * 13 * 32) // 6656 CTAs

#define SMEM_BYTES (HH_ * SSD_PITCH * 8 + HH_ * HHP * 16)  // 17200+26400 = 43600

// Gaussian(sigma=1.5, 11 taps), normalized (matches fp32 reference ~1e-7)
#define GW0 0.001028380f
#define GW1 0.007598758f
#define GW2 0.036000773f
#define GW3 0.109360703f
#define GW4 0.213005539f
#define GW5 0.266011725f

__device__ double g_slots[128];     // [0:64) mse partials, [64:128) ssim partials
__device__ unsigned int g_count;    // statically zero; reset by last CTA

__global__ __launch_bounds__(256, 5)
void k_main(const float* __restrict__ pred, const float* __restrict__ targ,
            float* __restrict__ out) {
    extern __shared__ char smem_raw[];
    float2* ssd = reinterpret_cast<float2*>(smem_raw);                       // [HH_][43]
    float4* hh  = reinterpret_cast<float4*>(smem_raw + HH_ * SSD_PITCH * 8); // [HH_][33]
    __shared__ float red[16];
    __shared__ int s_last;

    const float GW[11] = {GW0, GW1, GW2, GW3, GW4, GW5, GW4, GW3, GW2, GW1, GW0};

    const int t = threadIdx.x;                 // 256 threads
    const int lane = t & 31;
    const int wid = t >> 5;
    const int ox0 = blockIdx.x * TW;
    const int oy0 = blockIdx.y * TH;
    const float* P = pred + (size_t)blockIdx.z * (IMG * IMG);
    const float* T = targ + (size_t)blockIdx.z * (IMG * IMG);

    // ---- 1) halo load: 50 rows x 11 float4 groups, centered s' = p+t-1 ----
    // ox0 multiple of 32, IMG multiple of 4 => each float4 fully in/out of
    // range. OOB -> s'=0, d=0 (feeds only excluded SSIM outputs; d=0 adds
    // nothing to MSE).
    for (int idx = t; idx < HH_ * 11; idx += 256) {
        int r = idx / 11;
        int c4 = idx - r * 11;
        int gy = oy0 + r, gx = ox0 + c4 * 4;
        float4 p = make_float4(0.f, 0.f, 0.f, 0.f);
        float4 q = make_float4(0.f, 0.f, 0.f, 0.f);
        bool inb = (gy < IMG) && (gx <= IMG - 4);
        if (inb) {
            int o = gy * IMG + gx;
            p = *reinterpret_cast<const float4*>(P + o);
            q = *reinterpret_cast<const float4*>(T + o);
        }
        float cen = inb ? 1.0f : 0.0f;
        int c = c4 * 4;
        float2* row = ssd + r * SSD_PITCH;
        row[c + 0] = make_float2(p.x + q.x - cen, p.x - q.x);
        row[c + 1] = make_float2(p.y + q.y - cen, p.y - q.y);
        row[c + 2] = make_float2(p.z + q.z - cen, p.z - q.z);
        row[c + 3] = make_float2(p.w + q.w - cen, p.w - q.w);
    }
    __syncthreads();

    // ---- 2) fused MSE over owned 32x40 region (bands disjoint; rows >=512
    //         are OOB-zero so they contribute 0) ----
    const int tx = lane;
    const int y0 = wid * 5;                    // 8 warps x 5 rows = 40
    float msel = 0.0f;
#pragma unroll
    for (int j = 0; j < 5; j++) {
        float d = ssd[(y0 + j) * SSD_PITCH + tx].y;
        msel = fmaf(d, d, msel);
    }

    // ---- 3) horizontal pass: 13 row-quads (4 rows x 8 col-groups each) ----
    // Warp w handles quads w, w+8. Within a warp: r = quad*4 + (lane&3),
    // c0 = (lane>>2)*4 -> STS.128 bank = r + c0 + j, conflict-free.
    for (int quad = wid; quad < NQUAD; quad += 8) {
        int r = quad * 4 + (lane & 3);
        int c0 = (lane >> 2) * 4;
        if (r < HH_) {
            float as[4], ad[4], ass[4], add[4];
#pragma unroll
            for (int j = 0; j < 4; j++) { as[j] = ad[j] = ass[j] = add[j] = 0.0f; }
            const float2* row = ssd + r * SSD_PITCH;
#pragma unroll
            for (int i = 0; i < 14; i++) {
                float2 v = row[c0 + i];
                float ss = v.x * v.x, dd = v.y * v.y;
#pragma unroll
                for (int j = 0; j < 4; j++) {
                    int k = i - j;
                    if (k >= 0 && k < 11) {
                        as[j]  = fmaf(GW[k], v.x, as[j]);
                        ad[j]  = fmaf(GW[k], v.y, ad[j]);
                        ass[j] = fmaf(GW[k], ss,  ass[j]);
                        add[j] = fmaf(GW[k], dd,  add[j]);
                    }
                }
            }
            float4* hrow = hh + r * HHP;
#pragma unroll
            for (int j = 0; j < 4; j++)
                hrow[c0 + j] = make_float4(as[j], ad[j], ass[j], add[j]);
        }
    }
    __syncthreads();

    // ---- 4) vertical pass: 5 consecutive output rows per thread ----
    float bs[5], bd[5], bss[5], bdd[5];
#pragma unroll
    for (int j = 0; j < 5; j++) { bs[j] = bd[j] = bss[j] = bdd[j] = 0.0f; }
#pragma unroll
    for (int i = 0; i < 15; i++) {
        float4 v = hh[(y0 + i) * HHP + tx];
#pragma unroll
        for (int j = 0; j < 5; j++) {
            int k = i - j;
            if (k >= 0 && k < 11) {
                bs[j]  = fmaf(GW[k], v.x, bs[j]);
                bd[j]  = fmaf(GW[k], v.y, bd[j]);
                bss[j] = fmaf(GW[k], v.z, bss[j]);
                bdd[j] = fmaf(GW[k], v.w, bdd[j]);
            }
        }
    }

    // ---- 5) ssim map + partial sum ----
    const float C1 = 1e-4f;   // (0.01)^2
    const float C2 = 9e-4f;   // (0.03)^2
    float lsum = 0.0f;
    const int ox = ox0 + tx;
#pragma unroll
    for (int j = 0; j < 5; j++) {
        int oy = oy0 + y0 + j;
        if (ox < OUT && oy < OUT) {
            float bsf = bs[j] + 1.0f;              // mu1+mu2
            float A = bsf * bsf;
            float B = bd[j] * bd[j];
            float U = bss[j] - bs[j] * bs[j];      // sigma1^2+sigma2^2+2sigma12
            float V = bdd[j] - B;                  // sigma1^2+sigma2^2-2sigma12
            float num1 = 0.5f * (A - B) + C1;      // 2*mu1mu2 + C1
            float den1 = 0.5f * (A + B) + C1;      // mu1^2+mu2^2 + C1
            float num2 = 0.5f * (U - V) + C2;      // 2*sigma12 + C2
            float den2 = 0.5f * (U + V) + C2;      // sigma1+sigma2 + C2
            lsum += __fdividef(num1 * num2, den1 * den2 + 1e-6f);
        }
    }

    // ---- 6) block reduce (mse, ssim) -> slot atomics ----
#pragma unroll
    for (int off = 16; off > 0; off >>= 1) {
        msel += __shfl_down_sync(0xFFFFFFFFu, msel, off);
        lsum += __shfl_down_sync(0xFFFFFFFFu, lsum, off);
    }
    if (lane == 0) { red[wid] = msel; red[8 + wid] = lsum; }
    __syncthreads();
    if (t == 0) {
        float ms = 0.0f, ls = 0.0f;
#pragma unroll
        for (int w = 0; w < 8; w++) { ms += red[w]; ls += red[8 + w]; }
        int bid = blockIdx.x + 16 * blockIdx.y + 208 * blockIdx.z;
        int slot = bid & 63;
        atomicAdd(&g_slots[slot],      (double)ms);
        atomicAdd(&g_slots[64 + slot], (double)ls);
        __threadfence();
        unsigned int old = atomicAdd(&g_count, 1u);
        s_last = (old == NB - 1) ? 1 : 0;
    }
    __syncthreads();

    // ---- 7) last CTA: combine, write output, reset state for next replay ----
    if (s_last) {
        __threadfence();
        if (t < 32) {
            volatile double* vs = g_slots;
            double m = vs[t] + vs[t + 32];
            double s = vs[64 + t] + vs[96 + t];
#pragma unroll
            for (int off = 16; off > 0; off >>= 1) {
                m += __shfl_down_sync(0xFFFFFFFFu, m, off);
                s += __shfl_down_sync(0xFFFFFFFFu, s, off);
            }
            if (t == 0) {
                double mse_mean  = m / ((double)32 * IMG * IMG);
                double ssim_mean = s / ((double)32 * OUT * OUT);
                out[0] = (float)(0.6 * mse_mean + 0.4 * (1.0 - ssim_mean));
            }
        }
        __syncthreads();
        if (t < 128) ((volatile double*)g_slots)[t] = 0.0;
        if (t == 0) g_count = 0u;
    }
}

extern "C" void kernel_launch(void* const* d_in, const int* in_sizes, int n_in,
                              void* d_out, int out_size) {
    const float* pred = (const float*)d_in[0];
    const float* targ = (const float*)d_in[1];
    cudaFuncSetAttribute(k_main, cudaFuncAttributeMaxDynamicSharedMemorySize,
                         SMEM_BYTES);
    dim3 grid(16, 13, 32);   // x-tiles, y-bands of 40, batch
    k_main<<<grid, 256, SMEM_BYTES>>>(pred, targ, (float*)d_out);
}

// round 17
// speedup vs baseline: 1.8266x; 1.0861x over previous
#include <cuda_runtime.h>
#include <cuda_bf16.h>

// Fused MSE + SSIM loss, pred/target: [32,1,512,512] fp32.
// loss = 0.6*mean((p-t)^2) + 0.4*(1 - mean(ssim_map)); ssim via 11x11
// gaussian (sigma=1.5) VALID separable blur -> [32,502,502].
//
// One CTA per 32x40 output tile (grid 16x13x32 = 6656 CTAs), 256 threads,
// 5 CTAs/SM (smem 43.6KB, regs forced <=51).
// Centered s/d reparameterization: s' = p+t-1, d = p-t, channels kept as
// 64-bit lane pairs so ALL blur math runs on packed fma.rn.f32x2 (FFMA2):
//   ssd[r][c]       = pack(s', d)
//   hh[r][c]        = (pack(bs', bd), pack(bss', bdd))  [ulonglong2]
// Gaussian weight symmetry g[k]=g[10-k] -> only 6 packed weight registers.
// MSE folded into the halo-load phase (d in registers, no re-read).

#define IMG 512
#define OUT 502            // 512 - 10
#define TW  32             // tile width (outputs)
#define TH  40             // tile height (outputs)
#define HH_ 50             // TH + 10 (halo rows)
#define SSD_PITCH 43       // u64 elements per ssd row
#define HHP 33             // ulonglong2 elements per hh row
#define NQUAD 13           // ceil(HH_/4) row-quads for horizontal pass
#define NB  (16 * 13 * 32) // 6656 CTAs

#define SMEM_BYTES (HH_ * SSD_PITCH * 8 + HH_ * HHP * 16)  // 17200+26400 = 43600

// Gaussian(sigma=1.5, 11 taps), normalized (matches fp32 reference ~1e-7)
#define GW0 0.001028380f
#define GW1 0.007598758f
#define GW2 0.036000773f
#define GW3 0.109360703f
#define GW4 0.213005539f
#define GW5 0.266011725f

__device__ double g_slots[128];     // [0:64) mse partials, [64:128) ssim partials
__device__ unsigned int g_count;    // statically zero; reset by last CTA

// ---- packed f32x2 helpers (sm_103a) ----
__device__ __forceinline__ unsigned long long pack2(float a, float b) {
    unsigned long long r;
    asm("mov.b64 %0, {%1, %2};" : "=l"(r) : "f"(a), "f"(b));
    return r;
}
__device__ __forceinline__ void unpack2(float& a, float& b, unsigned long long v) {
    asm("mov.b64 {%0, %1}, %2;" : "=f"(a), "=f"(b) : "l"(v));
}
#define FMA2(acc, w, v) \
    asm("fma.rn.f32x2 %0, %1, %2, %0;" : "+l"(acc) : "l"(w), "l"(v))
#define MUL2(out, a, b) \
    asm("mul.rn.f32x2 %0, %1, %2;" : "=l"(out) : "l"(a), "l"(b))

__global__ __launch_bounds__(256, 5)
void k_main(const float* __restrict__ pred, const float* __restrict__ targ,
            float* __restrict__ out) {
    extern __shared__ char smem_raw[];
    unsigned long long* ssd = reinterpret_cast<unsigned long long*>(smem_raw); // [HH_][43]
    ulonglong2* hh = reinterpret_cast<ulonglong2*>(smem_raw + HH_ * SSD_PITCH * 8); // [HH_][33]
    __shared__ float red[16];
    __shared__ int s_last;

    const float GW[11] = {GW0, GW1, GW2, GW3, GW4, GW5, GW4, GW3, GW2, GW1, GW0};
    // 6 packed weights; index via symmetry min(k, 10-k)
    unsigned long long gwp[6];
#pragma unroll
    for (int k = 0; k < 6; k++) gwp[k] = pack2(GW[k], GW[k]);

    const int t = threadIdx.x;                 // 256 threads
    const int lane = t & 31;
    const int wid = t >> 5;
    const int ox0 = blockIdx.x * TW;
    const int oy0 = blockIdx.y * TH;
    const float* P = pred + (size_t)blockIdx.z * (IMG * IMG);
    const float* T = targ + (size_t)blockIdx.z * (IMG * IMG);

    // ---- 1) halo load (50 rows x 11 float4 groups) + fused MSE ----
    // ox0 multiple of 32, IMG multiple of 4 => each float4 fully in/out of
    // range. OOB -> s'=0, d=0 (feeds only excluded SSIM outputs; d=0 adds
    // nothing to MSE). MSE gated to the owned 32x40 region (r<TH, c4<8):
    // every image pixel is counted exactly once across the grid.
    float msel = 0.0f;
    for (int idx = t; idx < HH_ * 11; idx += 256) {
        int r = idx / 11;
        int c4 = idx - r * 11;
        int gy = oy0 + r, gx = ox0 + c4 * 4;
        float4 p = make_float4(0.f, 0.f, 0.f, 0.f);
        float4 q = make_float4(0.f, 0.f, 0.f, 0.f);
        bool inb = (gy < IMG) && (gx <= IMG - 4);
        if (inb) {
            int o = gy * IMG + gx;
            p = *reinterpret_cast<const float4*>(P + o);
            q = *reinterpret_cast<const float4*>(T + o);
        }
        float d0 = p.x - q.x, d1 = p.y - q.y, d2 = p.z - q.z, d3 = p.w - q.w;
        if (r < TH && c4 < 8) {
            msel = fmaf(d0, d0, msel);
            msel = fmaf(d1, d1, msel);
            msel = fmaf(d2, d2, msel);
            msel = fmaf(d3, d3, msel);
        }
        float cen = inb ? 1.0f : 0.0f;
        int c = c4 * 4;
        unsigned long long* row = ssd + r * SSD_PITCH;
        row[c + 0] = pack2(p.x + q.x - cen, d0);
        row[c + 1] = pack2(p.y + q.y - cen, d1);
        row[c + 2] = pack2(p.z + q.z - cen, d2);
        row[c + 3] = pack2(p.w + q.w - cen, d3);
    }
    __syncthreads();

    // ---- 2) horizontal pass: 13 row-quads (4 rows x 8 col-groups each) ----
    // Warp w handles quads w, w+8. r = quad*4 + (lane&3), c0 = (lane>>2)*4
    // -> conflict-free LDS.64 / STS.128. All math packed f32x2.
    for (int quad = wid; quad < NQUAD; quad += 8) {
        int r = quad * 4 + (lane & 3);
        int c0 = (lane >> 2) * 4;
        if (r < HH_) {
            unsigned long long a_sd[4], a_qq[4];
#pragma unroll
            for (int j = 0; j < 4; j++) { a_sd[j] = 0ull; a_qq[j] = 0ull; }
            const unsigned long long* row = ssd + r * SSD_PITCH;
#pragma unroll
            for (int i = 0; i < 14; i++) {
                unsigned long long v = row[c0 + i];
                unsigned long long vv;
                MUL2(vv, v, v);
#pragma unroll
                for (int j = 0; j < 4; j++) {
                    int k = i - j;
                    if (k >= 0 && k < 11) {
                        int ks = (k < 6) ? k : 10 - k;
                        FMA2(a_sd[j], gwp[ks], v);
                        FMA2(a_qq[j], gwp[ks], vv);
                    }
                }
            }
            ulonglong2* hrow = hh + r * HHP;
#pragma unroll
            for (int j = 0; j < 4; j++)
                hrow[c0 + j] = make_ulonglong2(a_sd[j], a_qq[j]);
        }
    }
    __syncthreads();

    // ---- 3) vertical pass: 5 consecutive output rows per thread ----
    const int tx = lane;
    const int y0 = wid * 5;                    // 8 warps x 5 rows = 40
    unsigned long long b_sd[5], b_qq[5];
#pragma unroll
    for (int j = 0; j < 5; j++) { b_sd[j] = 0ull; b_qq[j] = 0ull; }
#pragma unroll
    for (int i = 0; i < 15; i++) {
        ulonglong2 v = hh[(y0 + i) * HHP + tx];
#pragma unroll
        for (int j = 0; j < 5; j++) {
            int k = i - j;
            if (k >= 0 && k < 11) {
                int ks = (k < 6) ? k : 10 - k;
                FMA2(b_sd[j], gwp[ks], v.x);
                FMA2(b_qq[j], gwp[ks], v.y);
            }
        }
    }

    // ---- 4) ssim map + partial sum ----
    const float C1 = 1e-4f;   // (0.01)^2
    const float C2 = 9e-4f;   // (0.03)^2
    float lsum = 0.0f;
    const int ox = ox0 + tx;
#pragma unroll
    for (int j = 0; j < 5; j++) {
        int oy = oy0 + y0 + j;
        if (ox < OUT && oy < OUT) {
            float bs, bd, bss, bdd;
            unpack2(bs, bd, b_sd[j]);
            unpack2(bss, bdd, b_qq[j]);
            float bsf = bs + 1.0f;                 // mu1+mu2
            float A = bsf * bsf;
            float B = bd * bd;
            float U = bss - bs * bs;               // sig1^2+sig2^2+2sig12
            float V = bdd - B;                     // sig1^2+sig2^2-2sig12
            float num1 = 0.5f * (A - B) + C1;      // 2*mu1mu2 + C1
            float den1 = 0.5f * (A + B) + C1;      // mu1^2+mu2^2 + C1
            float num2 = 0.5f * (U - V) + C2;      // 2*sigma12 + C2
            float den2 = 0.5f * (U + V) + C2;      // sigma1+sigma2 + C2
            lsum += __fdividef(num1 * num2, den1 * den2 + 1e-6f);
        }
    }

    // ---- 5) block reduce (mse, ssim) -> slot atomics ----
#pragma unroll
    for (int off = 16; off > 0; off >>= 1) {
        msel += __shfl_down_sync(0xFFFFFFFFu, msel, off);
        lsum += __shfl_down_sync(0xFFFFFFFFu, lsum, off);
    }
    if (lane == 0) { red[wid] = msel; red[8 + wid] = lsum; }
    __syncthreads();
    if (t == 0) {
        float ms = 0.0f, ls = 0.0f;
#pragma unroll
        for (int w = 0; w < 8; w++) { ms += red[w]; ls += red[8 + w]; }
        int bid = blockIdx.x + 16 * blockIdx.y + 208 * blockIdx.z;
        int slot = bid & 63;
        atomicAdd(&g_slots[slot],      (double)ms);
        atomicAdd(&g_slots[64 + slot], (double)ls);
        __threadfence();
        unsigned int old = atomicAdd(&g_count, 1u);
        s_last = (old == NB - 1) ? 1 : 0;
    }
    __syncthreads();

    // ---- 6) last CTA: combine, write output, reset state for next replay ----
    if (s_last) {
        __threadfence();
        if (t < 32) {
            volatile double* vs = g_slots;
            double m = vs[t] + vs[t + 32];
            double s = vs[64 + t] + vs[96 + t];
#pragma unroll
            for (int off = 16; off > 0; off >>= 1) {
                m += __shfl_down_sync(0xFFFFFFFFu, m, off);
                s += __shfl_down_sync(0xFFFFFFFFu, s, off);
            }
            if (t == 0) {
                double mse_mean  = m / ((double)32 * IMG * IMG);
                double ssim_mean = s / ((double)32 * OUT * OUT);
                out[0] = (float)(0.6 * mse_mean + 0.4 * (1.0 - ssim_mean));
            }
        }
        __syncthreads();
        if (t < 128) ((volatile double*)g_slots)[t] = 0.0;
        if (t == 0) g_count = 0u;
    }
}

extern "C" void kernel_launch(void* const* d_in, const int* in_sizes, int n_in,
                              void* d_out, int out_size) {
    const float* pred = (const float*)d_in[0];
    const float* targ = (const float*)d_in[1];
    cudaFuncSetAttribute(k_main, cudaFuncAttributeMaxDynamicSharedMemorySize,
                         SMEM_BYTES);
    dim3 grid(16, 13, 32);   // x-tiles, y-bands of 40, batch
    k_main<<<grid, 256, SMEM_BYTES>>>(pred, targ, (float*)d_out);
}